// round 15
// baseline (speedup 1.0000x reference)
#include <cuda_runtime.h>
#include <cuda_bf16.h>
#include <math.h>

#define D_MODEL 1024
#define NH 16
#define HD 64
#define BATCH 2
#define SEQ 2048
#define MROWS (BATCH*SEQ)

// Scratch. q: scaled by 0.125*log2e + tf32-rounded [B,H,S,HD]. k: rounded.
// v: rounded TRANSPOSED [B,H,HD,S]. ctx: rounded [B*S, D_MODEL].
__device__ float g_q[BATCH*NH*SEQ*HD];
__device__ float g_k[BATCH*NH*SEQ*HD];
__device__ float g_v[BATCH*NH*SEQ*HD];
__device__ float g_ctx[MROWS*D_MODEL];
__device__ float g_xr[MROWS*D_MODEL];
__device__ float g_wr[4*D_MODEL*D_MODEL];

__device__ __forceinline__ unsigned f2tf(float x) {
    unsigned r;
    asm("cvt.rna.tf32.f32 %0, %1;" : "=r"(r) : "f"(x));
    return r;
}

__device__ __forceinline__ void mma8(float* c, uint4 a, uint2 b) {
    asm volatile(
        "mma.sync.aligned.m16n8k8.row.col.f32.tf32.tf32.f32 "
        "{%0,%1,%2,%3}, {%4,%5,%6,%7}, {%8,%9}, {%0,%1,%2,%3};"
        : "+f"(c[0]), "+f"(c[1]), "+f"(c[2]), "+f"(c[3])
        : "r"(a.x), "r"(a.y), "r"(a.z), "r"(a.w), "r"(b.x), "r"(b.y));
}

__device__ __forceinline__ uint4 ldsm4(unsigned a) {
    uint4 r;
    asm volatile("ldmatrix.sync.aligned.m8n8.x4.shared.b16 {%0,%1,%2,%3}, [%4];"
        : "=r"(r.x), "=r"(r.y), "=r"(r.z), "=r"(r.w) : "r"(a));
    return r;
}

__device__ __forceinline__ void cpa16(unsigned dst, const void* src) {
    asm volatile("cp.async.cg.shared.global [%0], [%1], 16;" :: "r"(dst), "l"(src));
}

// ============================================================================
// Prologue: round x and weights to tf32 bits
// ============================================================================
__global__ void round_tf32(const float4* s0, float4* d0,
                           const float4* s1, float4* d1,
                           const float4* s2, float4* d2,
                           const float4* s3, float4* d3,
                           const float4* s4, float4* d4)
{
    int z = blockIdx.y;
    const float4* s;
    float4* d;
    int n4;
    if (z == 0)      { s = s0; d = d0; n4 = MROWS * D_MODEL / 4; }
    else if (z == 1) { s = s1; d = d1; n4 = D_MODEL * D_MODEL / 4; }
    else if (z == 2) { s = s2; d = d2; n4 = D_MODEL * D_MODEL / 4; }
    else if (z == 3) { s = s3; d = d3; n4 = D_MODEL * D_MODEL / 4; }
    else             { s = s4; d = d4; n4 = D_MODEL * D_MODEL / 4; }
    for (int i = blockIdx.x * blockDim.x + threadIdx.x; i < n4;
         i += gridDim.x * blockDim.x) {
        float4 v = s[i];
        float4 r;
        r.x = __uint_as_float(f2tf(v.x));
        r.y = __uint_as_float(f2tf(v.y));
        r.z = __uint_as_float(f2tf(v.z));
        r.w = __uint_as_float(f2tf(v.w));
        d[i] = r;
    }
}

// ============================================================================
// TF32 GEMM: cp.async 3-stage -> ldmatrix. 4 warps (2x2), warp tile 64x64.
// Block tile 128x128, K chunks of 32. ONE barrier per chunk.
// ============================================================================
#define TBM 128
#define TBN 128
#define TBK 32
#define RST 144
#define TILE_B (128*RST)
#define STAGE_B (2*TILE_B)
#define GSMEM (3*STAGE_B)       // 110592
#define QSCALE 0.1803368801111244f   // 0.125 * log2(e)

__global__ __launch_bounds__(128, 2) void gemm_tc(
    const float* __restrict__ X,
    const float* __restrict__ W0, const float* __restrict__ W1, const float* __restrict__ W2,
    float* __restrict__ Y0, float* __restrict__ Y1, float* __restrict__ Y2,
    int proj_mode)
{
    extern __shared__ char gsm[];
    const unsigned sbase = (unsigned)__cvta_generic_to_shared(gsm);
    const int tid = threadIdx.x;
    const int wid = tid >> 5, lane = tid & 31;
    const int g = lane >> 2, tq = lane & 3;
    const int wm = wid & 1, wn = wid >> 1;      // 2 x 2 warp grid
    const int bm = blockIdx.y * TBM, bn = blockIdx.x * TBN;
    const int z = blockIdx.z;
    const float* W = (z == 0) ? W0 : (z == 1) ? W1 : W2;
    float* Y = (z == 0) ? Y0 : (z == 1) ? Y1 : Y2;

    float acc[4][8][4];
    #pragma unroll
    for (int i = 0; i < 4; i++)
        #pragma unroll
        for (int j = 0; j < 8; j++)
            #pragma unroll
            for (int r = 0; r < 4; r++) acc[i][j][r] = 0.f;

    auto stage = [&](int j, int s) {
        const int kt = j * TBK;
        unsigned ab = sbase + (unsigned)s * STAGE_B;
        unsigned bb = ab + TILE_B;
        #pragma unroll
        for (int t = 0; t < 8; t++) {
            int c = t * 128 + tid, row = c >> 3, k16 = c & 7;
            cpa16(ab + row * RST + k16 * 16,
                  X + (size_t)(bm + row) * D_MODEL + kt + k16 * 4);
            cpa16(bb + row * RST + k16 * 16,
                  W + (size_t)(bn + row) * D_MODEL + kt + k16 * 4);
        }
        asm volatile("cp.async.commit_group;");
    };

    const unsigned laneOffA = (unsigned)(((lane & 7) + ((lane >> 3) & 1) * 8) * RST
                            + ((lane >> 4) & 1) * 16);
    const unsigned laneOffB = (unsigned)((((lane >> 4) & 1) * 8 + (lane & 7)) * RST
                            + ((lane >> 3) & 1) * 16);

    stage(0, 0);
    stage(1, 1);
    const int NCH = D_MODEL / TBK;
    for (int j = 0; j < NCH; j++) {
        if (j < NCH - 1) asm volatile("cp.async.wait_group 1;");
        else             asm volatile("cp.async.wait_group 0;");
        __syncthreads();
        if (j + 2 < NCH) stage(j + 2, (j + 2) % 3);

        unsigned ab = sbase + (unsigned)(j % 3) * STAGE_B;
        unsigned bb = ab + TILE_B;
        const unsigned awBase = ab + (unsigned)(wm * 64) * RST + laneOffA;
        const unsigned bwBase = bb + (unsigned)(wn * 64) * RST + laneOffB;
        #pragma unroll
        for (int kk8 = 0; kk8 < 4; kk8++) {
            uint4 a[4];
            #pragma unroll
            for (int mt = 0; mt < 4; mt++)
                a[mt] = ldsm4(awBase + (unsigned)(mt * 16) * RST + kk8 * 32);
            uint2 bf[8];
            #pragma unroll
            for (int i = 0; i < 4; i++) {
                uint4 bq = ldsm4(bwBase + (unsigned)(i * 16) * RST + kk8 * 32);
                bf[2 * i + 0] = make_uint2(bq.x, bq.y);
                bf[2 * i + 1] = make_uint2(bq.z, bq.w);
            }
            #pragma unroll
            for (int mt = 0; mt < 4; mt++)
                #pragma unroll
                for (int nt = 0; nt < 8; nt++)
                    mma8(acc[mt][nt], a[mt], bf[nt]);
        }
        // no bottom barrier: 3-stage ring + top barrier make it redundant
    }

    #pragma unroll
    for (int mt = 0; mt < 4; mt++) {
        #pragma unroll
        for (int nt = 0; nt < 8; nt++) {
            int row0 = bm + wm * 64 + mt * 16 + g;
            int col = bn + wn * 64 + nt * 8 + tq * 2;
            #pragma unroll
            for (int hh2 = 0; hh2 < 2; hh2++) {
                int row = row0 + hh2 * 8;
                float v0 = acc[mt][nt][hh2 * 2 + 0];
                float v1 = acc[mt][nt][hh2 * 2 + 1];
                if (proj_mode) {
                    int b2 = row >> 11, s2 = row & (SEQ - 1);
                    int hh = col >> 6, d0 = col & 63;
                    float r0, r1;
                    if (z == 0) {            // q: fold 1/sqrt(64) * log2e
                        r0 = __uint_as_float(f2tf(v0 * QSCALE));
                        r1 = __uint_as_float(f2tf(v1 * QSCALE));
                    } else {
                        r0 = __uint_as_float(f2tf(v0));
                        r1 = __uint_as_float(f2tf(v1));
                    }
                    if (z == 2) {            // v: transposed [B,H,HD,S]
                        float* dst = Y + ((size_t)((b2 * NH + hh) * HD + d0)) * SEQ + s2;
                        dst[0] = r0; dst[SEQ] = r1;
                    } else {
                        float* dst = Y + ((size_t)((b2 * NH + hh) * SEQ + s2)) * HD + d0;
                        dst[0] = r0; dst[1] = r1;
                    }
                } else {
                    float* dst = Y + (size_t)row * D_MODEL + col;
                    dst[0] = v0; dst[1] = v1;
                }
            }
        }
    }
}

// ============================================================================
// Causal flash attention: cp.async double-buffered K/V + ldmatrix; shuffle-
// transposed P; exp2-domain softmax (Q pre-scaled by 0.125*log2e).
// ============================================================================
#define QT 128
#define KT 64
#define QST2 272
#define SQ_OFF 0
#define SK0_OFF 34816
#define SK1_OFF 52224
#define SV0_OFF 69632
#define SV1_OFF 87040
#define FSMEM 104448

__global__ __launch_bounds__(256, 2) void flash_kernel()
{
    extern __shared__ char smf[];
    const unsigned sbase = (unsigned)__cvta_generic_to_shared(smf);

    const int tid = threadIdx.x;
    const int w = tid >> 5, lane = tid & 31;
    const int g = lane >> 2, tq = lane & 3;
    const int bh = blockIdx.y;
    const int b = bh / NH, h = bh % NH;
    const int qt = (gridDim.x - 1 - blockIdx.x);
    const int q0 = qt * QT;

    const float* qbase = g_q + (size_t)(b * NH + h) * SEQ * HD + (size_t)q0 * HD;
    const float* kbase = g_k + (size_t)(b * NH + h) * SEQ * HD;
    const float* vtb   = g_v + (size_t)(b * NH + h) * SEQ * HD;

    const int ktiles = 2 * qt + 2;

    #pragma unroll
    for (int i = 0; i < 8; i++) {
        int u = i * 256 + tid, row = u >> 4, k16 = u & 15;
        cpa16(sbase + SQ_OFF + row * QST2 + k16 * 16, qbase + row * HD + k16 * 4);
    }
    asm volatile("cp.async.commit_group;");

    auto stage_kv = [&](int ktile, int buf) {
        const int kv0 = ktile * KT;
        unsigned kb = sbase + (buf ? SK1_OFF : SK0_OFF);
        unsigned vb = sbase + (buf ? SV1_OFF : SV0_OFF);
        #pragma unroll
        for (int i = 0; i < 4; i++) {
            int u = i * 256 + tid, row = u >> 4, k16 = u & 15;
            cpa16(kb + row * QST2 + k16 * 16,
                  kbase + (size_t)(kv0 + row) * HD + k16 * 4);
            cpa16(vb + row * QST2 + k16 * 16,
                  vtb + (size_t)row * SEQ + kv0 + k16 * 4);
        }
        asm volatile("cp.async.commit_group;");
    };

    stage_kv(0, 0);
    stage_kv(1, 1);

    float o[8][4];
    #pragma unroll
    for (int nt = 0; nt < 8; nt++)
        #pragma unroll
        for (int r = 0; r < 4; r++) o[nt][r] = 0.f;
    float m0 = -INFINITY, m1 = -INFINITY, l0 = 0.f, l1 = 0.f;

    const int prow = w * 16 + g;
    const int row0g = q0 + prow;
    const int row1g = row0g + 8;

    const unsigned laneOffA = (unsigned)(((lane & 7) + ((lane >> 3) & 1) * 8) * QST2
                            + ((lane >> 4) & 1) * 16);
    const unsigned laneOffB = (unsigned)((((lane >> 4) & 1) * 8 + (lane & 7)) * QST2
                            + ((lane >> 3) & 1) * 16);
    const unsigned awQ = sbase + SQ_OFF + (unsigned)(w * 16) * QST2 + laneOffA;

    const int src1 = (lane & ~3) | (tq >> 1);
    const int src2 = src1 + 2;
    const bool odd = tq & 1;

    for (int kt = 0; kt < ktiles; kt++) {
        const int kv0 = kt * KT;
        const int buf = kt & 1;
        asm volatile("cp.async.wait_group 1;");
        __syncthreads();

        const unsigned bwK = sbase + (buf ? SK1_OFF : SK0_OFF) + laneOffB;
        const unsigned bwV = sbase + (buf ? SV1_OFF : SV0_OFF) + laneOffB;

        float sc[8][4];
        #pragma unroll
        for (int nt = 0; nt < 8; nt++)
            #pragma unroll
            for (int r = 0; r < 4; r++) sc[nt][r] = 0.f;
        #pragma unroll
        for (int kk8 = 0; kk8 < 8; kk8++) {
            uint4 a = ldsm4(awQ + kk8 * 32);
            #pragma unroll
            for (int i = 0; i < 4; i++) {
                uint4 bq = ldsm4(bwK + (unsigned)(i * 16) * QST2 + kk8 * 32);
                mma8(sc[2 * i + 0], a, make_uint2(bq.x, bq.y));
                mma8(sc[2 * i + 1], a, make_uint2(bq.z, bq.w));
            }
        }

        const bool msk0 = (kv0 + KT - 1 > row0g);
        const bool msk1 = (kv0 + KT - 1 > row1g);
        if (msk0 | msk1) {
            #pragma unroll
            for (int nt = 0; nt < 8; nt++) {
                int c0 = kv0 + nt * 8 + tq * 2;
                if (msk0) {
                    if (c0     > row0g) sc[nt][0] = -1e30f;
                    if (c0 + 1 > row0g) sc[nt][1] = -1e30f;
                }
                if (msk1) {
                    if (c0     > row1g) sc[nt][2] = -1e30f;
                    if (c0 + 1 > row1g) sc[nt][3] = -1e30f;
                }
            }
        }

        float rm0 = -1e30f, rm1 = -1e30f;
        #pragma unroll
        for (int nt = 0; nt < 8; nt++) {
            rm0 = fmaxf(rm0, fmaxf(sc[nt][0], sc[nt][1]));
            rm1 = fmaxf(rm1, fmaxf(sc[nt][2], sc[nt][3]));
        }
        rm0 = fmaxf(rm0, __shfl_xor_sync(0xffffffffu, rm0, 1));
        rm0 = fmaxf(rm0, __shfl_xor_sync(0xffffffffu, rm0, 2));
        rm1 = fmaxf(rm1, __shfl_xor_sync(0xffffffffu, rm1, 1));
        rm1 = fmaxf(rm1, __shfl_xor_sync(0xffffffffu, rm1, 2));

        float nm0 = fmaxf(m0, rm0), nm1 = fmaxf(m1, rm1);
        float a0 = exp2f(m0 - nm0), a1 = exp2f(m1 - nm1);
        m0 = nm0; m1 = nm1;

        float rs0 = 0.f, rs1 = 0.f;
        #pragma unroll
        for (int nt = 0; nt < 8; nt++) {
            float p0 = exp2f(sc[nt][0] - nm0); sc[nt][0] = p0; rs0 += p0;
            float p1 = exp2f(sc[nt][1] - nm0); sc[nt][1] = p1; rs0 += p1;
            float p2 = exp2f(sc[nt][2] - nm1); sc[nt][2] = p2; rs1 += p2;
            float p3 = exp2f(sc[nt][3] - nm1); sc[nt][3] = p3; rs1 += p3;
        }
        rs0 += __shfl_xor_sync(0xffffffffu, rs0, 1);
        rs0 += __shfl_xor_sync(0xffffffffu, rs0, 2);
        rs1 += __shfl_xor_sync(0xffffffffu, rs1, 1);
        rs1 += __shfl_xor_sync(0xffffffffu, rs1, 2);
        l0 = l0 * a0 + rs0;
        l1 = l1 * a1 + rs1;

        #pragma unroll
        for (int nt = 0; nt < 8; nt++) {
            o[nt][0] *= a0; o[nt][1] *= a0;
            o[nt][2] *= a1; o[nt][3] *= a1;
        }

        #pragma unroll
        for (int kb = 0; kb < 8; kb++) {
            float x0 = __shfl_sync(0xffffffffu, sc[kb][0], src1);
            float x1 = __shfl_sync(0xffffffffu, sc[kb][1], src1);
            float x2 = __shfl_sync(0xffffffffu, sc[kb][2], src1);
            float x3 = __shfl_sync(0xffffffffu, sc[kb][3], src1);
            float y0 = __shfl_sync(0xffffffffu, sc[kb][0], src2);
            float y1 = __shfl_sync(0xffffffffu, sc[kb][1], src2);
            float y2 = __shfl_sync(0xffffffffu, sc[kb][2], src2);
            float y3 = __shfl_sync(0xffffffffu, sc[kb][3], src2);
            uint4 a;
            a.x = f2tf(odd ? x1 : x0);
            a.y = f2tf(odd ? x3 : x2);
            a.z = f2tf(odd ? y1 : y0);
            a.w = f2tf(odd ? y3 : y2);
            #pragma unroll
            for (int i = 0; i < 4; i++) {
                uint4 bq = ldsm4(bwV + (unsigned)(i * 16) * QST2 + kb * 32);
                mma8(o[2 * i + 0], a, make_uint2(bq.x, bq.y));
                mma8(o[2 * i + 1], a, make_uint2(bq.z, bq.w));
            }
        }
        __syncthreads();
        if (kt + 2 < ktiles) stage_kv(kt + 2, buf);
    }

    float inv0 = 1.f / l0, inv1 = 1.f / l1;
    #pragma unroll
    for (int nt = 0; nt < 8; nt++) {
        int colg = h * HD + nt * 8 + tq * 2;
        size_t r0 = (size_t)(b * SEQ + row0g) * D_MODEL + colg;
        size_t r1 = (size_t)(b * SEQ + row1g) * D_MODEL + colg;
        g_ctx[r0]     = __uint_as_float(f2tf(o[nt][0] * inv0));
        g_ctx[r0 + 1] = __uint_as_float(f2tf(o[nt][1] * inv0));
        g_ctx[r1]     = __uint_as_float(f2tf(o[nt][2] * inv1));
        g_ctx[r1 + 1] = __uint_as_float(f2tf(o[nt][3] * inv1));
    }
}

// ============================================================================
extern "C" void kernel_launch(void* const* d_in, const int* in_sizes, int n_in,
                              void* d_out, int out_size)
{
    const float* x  = (const float*)d_in[0];
    const float* qW = (const float*)d_in[1];
    const float* kW = (const float*)d_in[2];
    const float* vW = (const float*)d_in[3];
    const float* oW = (const float*)d_in[4];
    float* out = (float*)d_out;

    float *pq, *pk, *pv, *pctx, *pxr, *pwr;
    cudaGetSymbolAddress((void**)&pq, g_q);
    cudaGetSymbolAddress((void**)&pk, g_k);
    cudaGetSymbolAddress((void**)&pv, g_v);
    cudaGetSymbolAddress((void**)&pctx, g_ctx);
    cudaGetSymbolAddress((void**)&pxr, g_xr);
    cudaGetSymbolAddress((void**)&pwr, g_wr);
    float* pw0 = pwr;
    float* pw1 = pwr + D_MODEL * D_MODEL;
    float* pw2 = pwr + 2 * D_MODEL * D_MODEL;
    float* pw3 = pwr + 3 * D_MODEL * D_MODEL;

    cudaFuncSetAttribute(gemm_tc, cudaFuncAttributeMaxDynamicSharedMemorySize, GSMEM);
    cudaFuncSetAttribute(flash_kernel, cudaFuncAttributeMaxDynamicSharedMemorySize, FSMEM);

    round_tf32<<<dim3(512, 5), 256>>>(
        (const float4*)x,  (float4*)pxr,
        (const float4*)qW, (float4*)pw0,
        (const float4*)kW, (float4*)pw1,
        (const float4*)vW, (float4*)pw2,
        (const float4*)oW, (float4*)pw3);

    dim3 ggridQKV(D_MODEL / TBN, MROWS / TBM, 3);
    gemm_tc<<<ggridQKV, 128, GSMEM>>>(pxr, pw0, pw1, pw2, pq, pk, pv, 1);

    flash_kernel<<<dim3(SEQ / QT, BATCH * NH), 256, FSMEM>>>();

    dim3 ggridO(D_MODEL / TBN, MROWS / TBM, 1);
    gemm_tc<<<ggridO, 128, GSMEM>>>(pctx, pw3, pw3, pw3, out, out, out, 0);
}

// round 16
// speedup vs baseline: 1.0022x; 1.0022x over previous
#include <cuda_runtime.h>
#include <cuda_bf16.h>
#include <math.h>

#define D_MODEL 1024
#define NH 16
#define HD 64
#define BATCH 2
#define SEQ 2048
#define MROWS (BATCH*SEQ)

// Scratch. q: scaled by 0.125*log2e + tf32-rounded [B,H,S,HD]. k: rounded.
// v: rounded TRANSPOSED [B,H,HD,S]. ctx: rounded [B*S, D_MODEL].
__device__ float g_q[BATCH*NH*SEQ*HD];
__device__ float g_k[BATCH*NH*SEQ*HD];
__device__ float g_v[BATCH*NH*SEQ*HD];
__device__ float g_ctx[MROWS*D_MODEL];
__device__ float g_xr[MROWS*D_MODEL];
__device__ float g_wr[4*D_MODEL*D_MODEL];

__device__ __forceinline__ unsigned f2tf(float x) {
    unsigned r;
    asm("cvt.rna.tf32.f32 %0, %1;" : "=r"(r) : "f"(x));
    return r;
}

__device__ __forceinline__ void mma8(float* c, uint4 a, uint2 b) {
    asm volatile(
        "mma.sync.aligned.m16n8k8.row.col.f32.tf32.tf32.f32 "
        "{%0,%1,%2,%3}, {%4,%5,%6,%7}, {%8,%9}, {%0,%1,%2,%3};"
        : "+f"(c[0]), "+f"(c[1]), "+f"(c[2]), "+f"(c[3])
        : "r"(a.x), "r"(a.y), "r"(a.z), "r"(a.w), "r"(b.x), "r"(b.y));
}

__device__ __forceinline__ uint4 ldsm4(unsigned a) {
    uint4 r;
    asm volatile("ldmatrix.sync.aligned.m8n8.x4.shared.b16 {%0,%1,%2,%3}, [%4];"
        : "=r"(r.x), "=r"(r.y), "=r"(r.z), "=r"(r.w) : "r"(a));
    return r;
}

__device__ __forceinline__ void cpa16(unsigned dst, const void* src) {
    asm volatile("cp.async.cg.shared.global [%0], [%1], 16;" :: "r"(dst), "l"(src));
}

// ============================================================================
// Prologue: round x and weights to tf32 bits
// ============================================================================
__global__ void round_tf32(const float4* s0, float4* d0,
                           const float4* s1, float4* d1,
                           const float4* s2, float4* d2,
                           const float4* s3, float4* d3,
                           const float4* s4, float4* d4)
{
    int z = blockIdx.y;
    const float4* s;
    float4* d;
    int n4;
    if (z == 0)      { s = s0; d = d0; n4 = MROWS * D_MODEL / 4; }
    else if (z == 1) { s = s1; d = d1; n4 = D_MODEL * D_MODEL / 4; }
    else if (z == 2) { s = s2; d = d2; n4 = D_MODEL * D_MODEL / 4; }
    else if (z == 3) { s = s3; d = d3; n4 = D_MODEL * D_MODEL / 4; }
    else             { s = s4; d = d4; n4 = D_MODEL * D_MODEL / 4; }
    for (int i = blockIdx.x * blockDim.x + threadIdx.x; i < n4;
         i += gridDim.x * blockDim.x) {
        float4 v = s[i];
        float4 r;
        r.x = __uint_as_float(f2tf(v.x));
        r.y = __uint_as_float(f2tf(v.y));
        r.z = __uint_as_float(f2tf(v.z));
        r.w = __uint_as_float(f2tf(v.w));
        d[i] = r;
    }
}

// ============================================================================
// TF32 GEMM: cp.async 3-stage -> ldmatrix. 8 warps (2x4), warp tile 64x32.
// Block tile 128x128, K chunks of 32. ONE barrier per chunk.
// ============================================================================
#define TBM 128
#define TBN 128
#define TBK 32
#define RST 144
#define TILE_B (128*RST)
#define STAGE_B (2*TILE_B)
#define GSMEM (3*STAGE_B)       // 110592
#define QSCALE 0.1803368801111244f   // 0.125 * log2(e)

__global__ __launch_bounds__(256, 2) void gemm_tc(
    const float* __restrict__ X,
    const float* __restrict__ W0, const float* __restrict__ W1, const float* __restrict__ W2,
    float* __restrict__ Y0, float* __restrict__ Y1, float* __restrict__ Y2,
    int proj_mode)
{
    extern __shared__ char gsm[];
    const unsigned sbase = (unsigned)__cvta_generic_to_shared(gsm);
    const int tid = threadIdx.x;
    const int wid = tid >> 5, lane = tid & 31;
    const int g = lane >> 2, tq = lane & 3;
    const int wm = wid & 1, wn = wid >> 1;      // 2 x 4 warp grid
    const int bm = blockIdx.y * TBM, bn = blockIdx.x * TBN;
    const int z = blockIdx.z;
    const float* W = (z == 0) ? W0 : (z == 1) ? W1 : W2;
    float* Y = (z == 0) ? Y0 : (z == 1) ? Y1 : Y2;

    float acc[4][4][4];
    #pragma unroll
    for (int i = 0; i < 4; i++)
        #pragma unroll
        for (int j = 0; j < 4; j++)
            #pragma unroll
            for (int r = 0; r < 4; r++) acc[i][j][r] = 0.f;

    auto stage = [&](int j, int s) {
        const int kt = j * TBK;
        unsigned ab = sbase + (unsigned)s * STAGE_B;
        unsigned bb = ab + TILE_B;
        #pragma unroll
        for (int t = 0; t < 4; t++) {
            int c = t * 256 + tid, row = c >> 3, k16 = c & 7;
            cpa16(ab + row * RST + k16 * 16,
                  X + (size_t)(bm + row) * D_MODEL + kt + k16 * 4);
            cpa16(bb + row * RST + k16 * 16,
                  W + (size_t)(bn + row) * D_MODEL + kt + k16 * 4);
        }
        asm volatile("cp.async.commit_group;");
    };

    const unsigned laneOffA = (unsigned)(((lane & 7) + ((lane >> 3) & 1) * 8) * RST
                            + ((lane >> 4) & 1) * 16);
    const unsigned laneOffB = (unsigned)((((lane >> 4) & 1) * 8 + (lane & 7)) * RST
                            + ((lane >> 3) & 1) * 16);

    stage(0, 0);
    stage(1, 1);
    const int NCH = D_MODEL / TBK;
    for (int j = 0; j < NCH; j++) {
        if (j < NCH - 1) asm volatile("cp.async.wait_group 1;");
        else             asm volatile("cp.async.wait_group 0;");
        __syncthreads();
        if (j + 2 < NCH) stage(j + 2, (j + 2) % 3);

        unsigned ab = sbase + (unsigned)(j % 3) * STAGE_B;
        unsigned bb = ab + TILE_B;
        const unsigned awBase = ab + (unsigned)(wm * 64) * RST + laneOffA;
        const unsigned bwBase = bb + (unsigned)(wn * 32) * RST + laneOffB;
        #pragma unroll
        for (int kk8 = 0; kk8 < 4; kk8++) {
            uint4 a[4];
            #pragma unroll
            for (int mt = 0; mt < 4; mt++)
                a[mt] = ldsm4(awBase + (unsigned)(mt * 16) * RST + kk8 * 32);
            uint4 b0 = ldsm4(bwBase + kk8 * 32);
            uint4 b1 = ldsm4(bwBase + (unsigned)(16 * RST) + kk8 * 32);
            uint2 bf[4];
            bf[0] = make_uint2(b0.x, b0.y);
            bf[1] = make_uint2(b0.z, b0.w);
            bf[2] = make_uint2(b1.x, b1.y);
            bf[3] = make_uint2(b1.z, b1.w);
            #pragma unroll
            for (int mt = 0; mt < 4; mt++)
                #pragma unroll
                for (int nt = 0; nt < 4; nt++)
                    mma8(acc[mt][nt], a[mt], bf[nt]);
        }
        // no bottom barrier: 3-stage ring + top barrier make it redundant
    }

    #pragma unroll
    for (int mt = 0; mt < 4; mt++) {
        #pragma unroll
        for (int nt = 0; nt < 4; nt++) {
            int row0 = bm + wm * 64 + mt * 16 + g;
            int col = bn + wn * 32 + nt * 8 + tq * 2;
            #pragma unroll
            for (int hh2 = 0; hh2 < 2; hh2++) {
                int row = row0 + hh2 * 8;
                float v0 = acc[mt][nt][hh2 * 2 + 0];
                float v1 = acc[mt][nt][hh2 * 2 + 1];
                if (proj_mode) {
                    int b2 = row >> 11, s2 = row & (SEQ - 1);
                    int hh = col >> 6, d0 = col & 63;
                    float r0, r1;
                    if (z == 0) {            // q: fold 1/sqrt(64) * log2e
                        r0 = __uint_as_float(f2tf(v0 * QSCALE));
                        r1 = __uint_as_float(f2tf(v1 * QSCALE));
                    } else {
                        r0 = __uint_as_float(f2tf(v0));
                        r1 = __uint_as_float(f2tf(v1));
                    }
                    if (z == 2) {            // v: transposed [B,H,HD,S]
                        float* dst = Y + ((size_t)((b2 * NH + hh) * HD + d0)) * SEQ + s2;
                        dst[0] = r0; dst[SEQ] = r1;
                    } else {
                        float* dst = Y + ((size_t)((b2 * NH + hh) * SEQ + s2)) * HD + d0;
                        dst[0] = r0; dst[1] = r1;
                    }
                } else {
                    float* dst = Y + (size_t)row * D_MODEL + col;
                    dst[0] = v0; dst[1] = v1;
                }
            }
        }
    }
}

// ============================================================================
// Causal flash attention: Q in registers; 3-buffer KV ring (ONE barrier per
// tile); cp.async + ldmatrix; shuffle-transposed P; exp2-domain softmax.
// Ring buffer i at i*KVB: K (64x272) then V^T (64x272).
// ============================================================================
#define QT 128
#define KT 64
#define QST2 272
#define KVB 34816                  // (64+64)*272
#define FSMEM (3*KVB)              // 104448

__global__ __launch_bounds__(256, 2) void flash_kernel()
{
    extern __shared__ char smf[];
    const unsigned sbase = (unsigned)__cvta_generic_to_shared(smf);

    const int tid = threadIdx.x;
    const int w = tid >> 5, lane = tid & 31;
    const int g = lane >> 2, tq = lane & 3;
    const int bh = blockIdx.y;
    const int b = bh / NH, h = bh % NH;
    const int qt = (gridDim.x - 1 - blockIdx.x);
    const int q0 = qt * QT;

    const float* qbase = g_q + (size_t)(b * NH + h) * SEQ * HD + (size_t)q0 * HD;
    const float* kbase = g_k + (size_t)(b * NH + h) * SEQ * HD;
    const float* vtb   = g_v + (size_t)(b * NH + h) * SEQ * HD;

    const int ktiles = 2 * qt + 2;

    const unsigned laneOffA = (unsigned)(((lane & 7) + ((lane >> 3) & 1) * 8) * QST2
                            + ((lane >> 4) & 1) * 16);
    const unsigned laneOffB = (unsigned)((((lane >> 4) & 1) * 8 + (lane & 7)) * QST2
                            + ((lane >> 3) & 1) * 16);

    // --- stage Q transiently into ring[2], extract to registers ---
    {
        const unsigned qoff = sbase + 2u * KVB;
        #pragma unroll
        for (int i = 0; i < 8; i++) {
            int u = i * 256 + tid, row = u >> 4, k16 = u & 15;
            // Q tile is 128 rows x 64 cols; rows 0..63 in K slot, 64..127 in V slot
            cpa16(qoff + row * QST2 + k16 * 16, qbase + row * HD + k16 * 4);
        }
        asm volatile("cp.async.commit_group;");
        asm volatile("cp.async.wait_group 0;");
        __syncthreads();
    }
    uint4 qf[8];
    {
        const unsigned awQ = sbase + 2u * KVB + (unsigned)(w * 16) * QST2 + laneOffA;
        #pragma unroll
        for (int kk8 = 0; kk8 < 8; kk8++)
            qf[kk8] = ldsm4(awQ + kk8 * 32);
        __syncthreads();   // all warps done reading ring[2] before KV(2) lands
    }

    auto stage_kv = [&](int ktile) {
        const int kv0 = ktile * KT;
        unsigned base = sbase + (unsigned)(ktile % 3) * KVB;
        #pragma unroll
        for (int i = 0; i < 4; i++) {
            int u = i * 256 + tid, row = u >> 4, k16 = u & 15;
            cpa16(base + row * QST2 + k16 * 16,
                  kbase + (size_t)(kv0 + row) * HD + k16 * 4);
            cpa16(base + 64u * QST2 + row * QST2 + k16 * 16,
                  vtb + (size_t)row * SEQ + kv0 + k16 * 4);
        }
        asm volatile("cp.async.commit_group;");
    };

    stage_kv(0);
    stage_kv(1);

    float o[8][4];
    #pragma unroll
    for (int nt = 0; nt < 8; nt++)
        #pragma unroll
        for (int r = 0; r < 4; r++) o[nt][r] = 0.f;
    float m0 = -INFINITY, m1 = -INFINITY, l0 = 0.f, l1 = 0.f;

    const int prow = w * 16 + g;
    const int row0g = q0 + prow;
    const int row1g = row0g + 8;

    const int src1 = (lane & ~3) | (tq >> 1);
    const int src2 = src1 + 2;
    const bool odd = tq & 1;

    for (int kt = 0; kt < ktiles; kt++) {
        const int kv0 = kt * KT;
        asm volatile("cp.async.wait_group 1;");
        __syncthreads();                       // single barrier per tile
        if (kt + 2 < ktiles) stage_kv(kt + 2); // ring[(kt+2)%3] drained by barrier

        const unsigned ring = sbase + (unsigned)(kt % 3) * KVB;
        const unsigned bwK = ring + laneOffB;
        const unsigned bwV = ring + 64u * QST2 + laneOffB;

        // S = Q K^T
        float sc[8][4];
        #pragma unroll
        for (int nt = 0; nt < 8; nt++)
            #pragma unroll
            for (int r = 0; r < 4; r++) sc[nt][r] = 0.f;
        #pragma unroll
        for (int kk8 = 0; kk8 < 8; kk8++) {
            #pragma unroll
            for (int i = 0; i < 4; i++) {
                uint4 bq = ldsm4(bwK + (unsigned)(i * 16) * QST2 + kk8 * 32);
                mma8(sc[2 * i + 0], qf[kk8], make_uint2(bq.x, bq.y));
                mma8(sc[2 * i + 1], qf[kk8], make_uint2(bq.z, bq.w));
            }
        }

        const bool msk0 = (kv0 + KT - 1 > row0g);
        const bool msk1 = (kv0 + KT - 1 > row1g);
        if (msk0 | msk1) {
            #pragma unroll
            for (int nt = 0; nt < 8; nt++) {
                int c0 = kv0 + nt * 8 + tq * 2;
                if (msk0) {
                    if (c0     > row0g) sc[nt][0] = -1e30f;
                    if (c0 + 1 > row0g) sc[nt][1] = -1e30f;
                }
                if (msk1) {
                    if (c0     > row1g) sc[nt][2] = -1e30f;
                    if (c0 + 1 > row1g) sc[nt][3] = -1e30f;
                }
            }
        }

        float rm0 = -1e30f, rm1 = -1e30f;
        #pragma unroll
        for (int nt = 0; nt < 8; nt++) {
            rm0 = fmaxf(rm0, fmaxf(sc[nt][0], sc[nt][1]));
            rm1 = fmaxf(rm1, fmaxf(sc[nt][2], sc[nt][3]));
        }
        rm0 = fmaxf(rm0, __shfl_xor_sync(0xffffffffu, rm0, 1));
        rm0 = fmaxf(rm0, __shfl_xor_sync(0xffffffffu, rm0, 2));
        rm1 = fmaxf(rm1, __shfl_xor_sync(0xffffffffu, rm1, 1));
        rm1 = fmaxf(rm1, __shfl_xor_sync(0xffffffffu, rm1, 2));

        float nm0 = fmaxf(m0, rm0), nm1 = fmaxf(m1, rm1);
        float a0 = exp2f(m0 - nm0), a1 = exp2f(m1 - nm1);
        m0 = nm0; m1 = nm1;

        float rs0 = 0.f, rs1 = 0.f;
        #pragma unroll
        for (int nt = 0; nt < 8; nt++) {
            float p0 = exp2f(sc[nt][0] - nm0); sc[nt][0] = p0; rs0 += p0;
            float p1 = exp2f(sc[nt][1] - nm0); sc[nt][1] = p1; rs0 += p1;
            float p2 = exp2f(sc[nt][2] - nm1); sc[nt][2] = p2; rs1 += p2;
            float p3 = exp2f(sc[nt][3] - nm1); sc[nt][3] = p3; rs1 += p3;
        }
        rs0 += __shfl_xor_sync(0xffffffffu, rs0, 1);
        rs0 += __shfl_xor_sync(0xffffffffu, rs0, 2);
        rs1 += __shfl_xor_sync(0xffffffffu, rs1, 1);
        rs1 += __shfl_xor_sync(0xffffffffu, rs1, 2);
        l0 = l0 * a0 + rs0;
        l1 = l1 * a1 + rs1;

        #pragma unroll
        for (int nt = 0; nt < 8; nt++) {
            o[nt][0] *= a0; o[nt][1] *= a0;
            o[nt][2] *= a1; o[nt][3] *= a1;
        }

        // O += P V: P a-frags via in-warp shuffle transpose
        #pragma unroll
        for (int kb = 0; kb < 8; kb++) {
            float x0 = __shfl_sync(0xffffffffu, sc[kb][0], src1);
            float x1 = __shfl_sync(0xffffffffu, sc[kb][1], src1);
            float x2 = __shfl_sync(0xffffffffu, sc[kb][2], src1);
            float x3 = __shfl_sync(0xffffffffu, sc[kb][3], src1);
            float y0 = __shfl_sync(0xffffffffu, sc[kb][0], src2);
            float y1 = __shfl_sync(0xffffffffu, sc[kb][1], src2);
            float y2 = __shfl_sync(0xffffffffu, sc[kb][2], src2);
            float y3 = __shfl_sync(0xffffffffu, sc[kb][3], src2);
            uint4 a;
            a.x = f2tf(odd ? x1 : x0);
            a.y = f2tf(odd ? x3 : x2);
            a.z = f2tf(odd ? y1 : y0);
            a.w = f2tf(odd ? y3 : y2);
            #pragma unroll
            for (int i = 0; i < 4; i++) {
                uint4 bq = ldsm4(bwV + (unsigned)(i * 16) * QST2 + kb * 32);
                mma8(o[2 * i + 0], a, make_uint2(bq.x, bq.y));
                mma8(o[2 * i + 1], a, make_uint2(bq.z, bq.w));
            }
        }
        // no bottom barrier: ring-3 + top barrier make it redundant
    }

    float inv0 = 1.f / l0, inv1 = 1.f / l1;
    #pragma unroll
    for (int nt = 0; nt < 8; nt++) {
        int colg = h * HD + nt * 8 + tq * 2;
        size_t r0 = (size_t)(b * SEQ + row0g) * D_MODEL + colg;
        size_t r1 = (size_t)(b * SEQ + row1g) * D_MODEL + colg;
        g_ctx[r0]     = __uint_as_float(f2tf(o[nt][0] * inv0));
        g_ctx[r0 + 1] = __uint_as_float(f2tf(o[nt][1] * inv0));
        g_ctx[r1]     = __uint_as_float(f2tf(o[nt][2] * inv1));
        g_ctx[r1 + 1] = __uint_as_float(f2tf(o[nt][3] * inv1));
    }
}

// ============================================================================
extern "C" void kernel_launch(void* const* d_in, const int* in_sizes, int n_in,
                              void* d_out, int out_size)
{
    const float* x  = (const float*)d_in[0];
    const float* qW = (const float*)d_in[1];
    const float* kW = (const float*)d_in[2];
    const float* vW = (const float*)d_in[3];
    const float* oW = (const float*)d_in[4];
    float* out = (float*)d_out;

    float *pq, *pk, *pv, *pctx, *pxr, *pwr;
    cudaGetSymbolAddress((void**)&pq, g_q);
    cudaGetSymbolAddress((void**)&pk, g_k);
    cudaGetSymbolAddress((void**)&pv, g_v);
    cudaGetSymbolAddress((void**)&pctx, g_ctx);
    cudaGetSymbolAddress((void**)&pxr, g_xr);
    cudaGetSymbolAddress((void**)&pwr, g_wr);
    float* pw0 = pwr;
    float* pw1 = pwr + D_MODEL * D_MODEL;
    float* pw2 = pwr + 2 * D_MODEL * D_MODEL;
    float* pw3 = pwr + 3 * D_MODEL * D_MODEL;

    cudaFuncSetAttribute(gemm_tc, cudaFuncAttributeMaxDynamicSharedMemorySize, GSMEM);
    cudaFuncSetAttribute(flash_kernel, cudaFuncAttributeMaxDynamicSharedMemorySize, FSMEM);

    round_tf32<<<dim3(512, 5), 256>>>(
        (const float4*)x,  (float4*)pxr,
        (const float4*)qW, (float4*)pw0,
        (const float4*)kW, (float4*)pw1,
        (const float4*)vW, (float4*)pw2,
        (const float4*)oW, (float4*)pw3);

    dim3 ggridQKV(D_MODEL / TBN, MROWS / TBM, 3);
    gemm_tc<<<ggridQKV, 256, GSMEM>>>(pxr, pw0, pw1, pw2, pq, pk, pv, 1);

    flash_kernel<<<dim3(SEQ / QT, BATCH * NH), 256, FSMEM>>>();

    dim3 ggridO(D_MODEL / TBN, MROWS / TBM, 1);
    gemm_tc<<<ggridO, 256, GSMEM>>>(pctx, pw3, pw3, pw3, out, out, out, 0);
}